// round 14
// baseline (speedup 1.0000x reference)
#include <cuda_runtime.h>
#include <cuda_fp16.h>
#include <cstdint>

// ---------------- problem constants ----------------
#define N_NODES  50000
#define E_MAX    450000
#define NFEAT    512
#define NHID     64
#define NHEADS   8
#define NOUT     128
#define X2DIM    512

// ---------------- device scratch ----------------
__device__ __half g_hh [(size_t)N_NODES * X2DIM];   // layer-1 head features, fp16
__device__ __half g_hml[(size_t)N_NODES * 256];     // fp16: [:,0:128]=h_mu, [:,128:256]=h_lv
__device__ float g_s1  [N_NODES * NHEADS];
__device__ float g_s2  [N_NODES * NHEADS];
__device__ float g_smu1[N_NODES], g_smu2[N_NODES], g_slv1[N_NODES], g_slv2[N_NODES];
__device__ int   g_rowptr[N_NODES + 1];
__device__ int   g_col [E_MAX];
__device__ int   g_cnt [N_NODES];
__device__ int   g_cursor[N_NODES];

// fp16 activations (single limb), fp16 weights
__device__ __half g_xh [(size_t)N_NODES * NFEAT];
__device__ __half g_x2h[(size_t)N_NODES * X2DIM];
__device__ __half g_bt1[512 * 512];                 // Ws^T        [512,512]
__device__ __half g_bt2[256 * 512];                 // [muW;lvW]^T [256,512]

// ---------------- PTX helpers (target-generic, sm_80+) ----------------
__device__ __forceinline__ unsigned smem_u32(const void* p) {
    unsigned r;
    asm("{ .reg .u64 t; cvta.to.shared.u64 t, %1; cvt.u32.u64 %0, t; }"
        : "=r"(r) : "l"(p));
    return r;
}
__device__ __forceinline__ void cp16(unsigned dst, const void* src, int srcsz) {
    asm volatile("cp.async.cg.shared.global [%0], [%1], 16, %2;"
                 :: "r"(dst), "l"(src), "r"(srcsz) : "memory");
}
__device__ __forceinline__ void cp_commit() {
    asm volatile("cp.async.commit_group;" ::: "memory");
}
__device__ __forceinline__ void ldsm4(unsigned& r0, unsigned& r1, unsigned& r2,
                                      unsigned& r3, unsigned a) {
    asm volatile("ldmatrix.sync.aligned.m8n8.x4.shared.b16 {%0,%1,%2,%3}, [%4];"
                 : "=r"(r0), "=r"(r1), "=r"(r2), "=r"(r3) : "r"(a));
}
__device__ __forceinline__ void mma16816(float* d, const unsigned* a, const unsigned* b) {
    asm volatile(
        "mma.sync.aligned.m16n8k16.row.col.f32.f16.f16.f32 "
        "{%0,%1,%2,%3}, {%4,%5,%6,%7}, {%8,%9}, {%0,%1,%2,%3};"
        : "+f"(d[0]), "+f"(d[1]), "+f"(d[2]), "+f"(d[3])
        : "r"(a[0]), "r"(a[1]), "r"(a[2]), "r"(a[3]), "r"(b[0]), "r"(b[1]));
}
// swizzled byte offset inside a tile whose rows are 64 fp16 = 128B
__device__ __forceinline__ unsigned aoff(int r, int k) {
    return (unsigned)((r << 7) + (((((k >> 3) ^ r) & 7)) << 4) + ((k & 7) << 1));
}

// ---------------- CSR construction ----------------
__global__ void zero_kernel(int n) {
    int i = blockIdx.x * blockDim.x + threadIdx.x;
    if (i < n) {
        g_cnt[i] = 0; g_cursor[i] = 0;
        g_smu1[i] = 0.f; g_smu2[i] = 0.f;
        g_slv1[i] = 0.f; g_slv2[i] = 0.f;
    }
}
__global__ void hist_kernel(const int* __restrict__ ei, int E) {
    int e = blockIdx.x * blockDim.x + threadIdx.x;
    if (e < E) atomicAdd(&g_cnt[ei[e]], 1);
}
// one-pass scan: 1024 threads, each owns a contiguous chunk
__global__ __launch_bounds__(1024) void scan_kernel(int n) {
    __shared__ int sh[1024];
    const int t = threadIdx.x;
    const int per = (n + 1023) / 1024;
    const int lo = min(t * per, n), hi = min(lo + per, n);
    int sum = 0;
    for (int i = lo; i < hi; i++) sum += g_cnt[i];
    sh[t] = sum;
    __syncthreads();
    for (int off = 1; off < 1024; off <<= 1) {
        int v = (t >= off) ? sh[t - off] : 0;
        __syncthreads();
        sh[t] += v;
        __syncthreads();
    }
    int run = sh[t] - sum;          // exclusive offset for this chunk
    for (int i = lo; i < hi; i++) {
        g_rowptr[i] = run;
        run += g_cnt[i];
    }
    if (t == 1023) g_rowptr[n] = sh[1023];
}
__global__ void fill_kernel(const int* __restrict__ ei, int E) {
    int e = blockIdx.x * blockDim.x + threadIdx.x;
    if (e < E) {
        int s = ei[e];
        int d = ei[E + e];
        int p = atomicAdd(&g_cursor[s], 1);
        g_col[g_rowptr[s] + p] = d;
    }
}

// ---------------- conversions ----------------
__global__ void convert_x_kernel(const float* __restrict__ x, int n4) {
    int i = blockIdx.x * blockDim.x + threadIdx.x;
    if (i >= n4) return;
    float4 v = ((const float4*)x)[i];
    ((__half2*)g_xh)[i * 2]     = __floats2half2_rn(v.x, v.y);
    ((__half2*)g_xh)[i * 2 + 1] = __floats2half2_rn(v.z, v.w);
}

__global__ void convert_w_kernel(const float* __restrict__ Ws,
                                 const float* __restrict__ muW,
                                 const float* __restrict__ lvW) {
    int i = blockIdx.x * blockDim.x + threadIdx.x;
    float v;
    __half* p;
    if (i < 512 * 512) {
        int row = i >> 9, k = i & 511;            // row = h*64 + n
        int h = row >> 6, n = row & 63;
        v = Ws[((size_t)h * 512 + k) * 64 + n];
        p = g_bt1 + i;
    } else if (i < 512 * 512 + 256 * 512) {
        int j = i - 512 * 512;
        int n = j >> 9, k = j & 511;
        v = (n < 128) ? muW[(size_t)k * 128 + n]
                      : lvW[(size_t)k * 128 + (n - 128)];
        p = g_bt2 + j;
    } else return;
    *p = __float2half_rn(v);
}

// ---------------- HMMA fp16 GEMM + fused attention-scalar epilogue ---------
// MODE 1: layer-1. C = g_hh; per-warp exact s1/s2 dots -> direct store.
// MODE 2: layer-2. C = g_hml; partial dots -> atomicAdd into g_smu*/g_slv*.
// Stage: A 16K | B 16K = 32KB; 3 stages = 96KB -> 2 CTAs/SM.
#define KC 64
#define STAGE 32768
#define NSTAGE 3

__device__ __forceinline__ void load_chunk(
    unsigned st, const __half* __restrict__ A, const __half* __restrict__ B,
    int m0, int k0, int M, int tid)
{
#pragma unroll
    for (int it = 0; it < 4; it++) {
        int idx = it * 256 + tid;
        int r = idx >> 3, c = idx & 7;
        unsigned d = st + (unsigned)((r << 7) + (((c ^ (r & 7)) & 7) << 4));
        int grow = m0 + r;
        int sz = (grow < M) ? 16 : 0;
        if (grow >= M) grow = M - 1;
        cp16(d,         A + (size_t)grow * 512 + k0 + c * 8, sz);
        cp16(d + 16384, B + (size_t)r * 512 + k0 + c * 8, 16);
    }
}

template <int MODE>
__global__ __launch_bounds__(256) void gemm_tc(
    const __half* __restrict__ A, const __half* __restrict__ Bg,
    __half* __restrict__ C, int M, int ldc,
    const float* __restrict__ av1, const float* __restrict__ av2)
{
    extern __shared__ char smem[];
    const unsigned sbase = smem_u32(smem);
    const int tid = threadIdx.x, lane = tid & 31, wid = tid >> 5;
    const int m0 = blockIdx.y * 128;
    const int nb = blockIdx.x * 128;
    const __half* B = Bg + (size_t)nb * 512;
    const int wm = (wid & 3) * 32, wn = (wid >> 2) * 64;

    float acc[2][8][4];
#pragma unroll
    for (int i = 0; i < 2; i++)
#pragma unroll
        for (int j = 0; j < 8; j++)
#pragma unroll
            for (int q = 0; q < 4; q++) acc[i][j][q] = 0.f;

    load_chunk(sbase,         A, B, m0, 0,  M, tid);
    cp_commit();
    load_chunk(sbase + STAGE, A, B, m0, KC, M, tid);
    cp_commit();

    for (int kc = 0; kc < 8; kc++) {
        if (kc < 7)
            asm volatile("cp.async.wait_group 1;" ::: "memory");
        else
            asm volatile("cp.async.wait_group 0;" ::: "memory");
        __syncthreads();
        if (kc + 2 < 8) {
            load_chunk(sbase + ((kc + 2) % NSTAGE) * STAGE, A, B,
                       m0, (kc + 2) * KC, M, tid);
            cp_commit();
        }
        const unsigned st = sbase + (kc % NSTAGE) * STAGE;
#pragma unroll
        for (int kk = 0; kk < 4; kk++) {
            const int k = kk * 16;
            int ar = lane & 15;
            int ac = k + ((lane >> 4) << 3);
            unsigned ah[2][4];
            ldsm4(ah[0][0], ah[0][1], ah[0][2], ah[0][3], st + aoff(wm + ar, ac));
            ldsm4(ah[1][0], ah[1][1], ah[1][2], ah[1][3], st + aoff(wm + 16 + ar, ac));
            int br = (lane & 7) + ((lane >> 4) << 3);
            int bc = k + (((lane >> 3) & 1) << 3);
            unsigned b[8][2];
#pragma unroll
            for (int q = 0; q < 4; q++)
                ldsm4(b[2*q][0], b[2*q][1], b[2*q+1][0], b[2*q+1][1],
                      st + 16384 + aoff(wn + 16 * q + br, bc));
#pragma unroll
            for (int mt = 0; mt < 2; mt++)
#pragma unroll
                for (int nt = 0; nt < 8; nt++)
                    mma16816(acc[mt][nt], ah[mt], b[nt]);
        }
    }

    // ---- store C ----
#pragma unroll
    for (int mt = 0; mt < 2; mt++) {
        int r0 = m0 + wm + mt * 16 + (lane >> 2);
#pragma unroll
        for (int nt = 0; nt < 8; nt++) {
            int c0 = nb + wn + nt * 8 + (lane & 3) * 2;
            if (r0 < M)
                *(__half2*)&C[(size_t)r0 * ldc + c0] =
                    __floats2half2_rn(acc[mt][nt][0], acc[mt][nt][1]);
            if (r0 + 8 < M)
                *(__half2*)&C[(size_t)(r0 + 8) * ldc + c0] =
                    __floats2half2_rn(acc[mt][nt][2], acc[mt][nt][3]);
        }
    }

    // ---- fused attention-scalar dots from fp32 accumulators ----
    if (MODE == 1) {
        const int h = (nb + wn) >> 6;
        float a1v[16], a2v[16];
#pragma unroll
        for (int nt = 0; nt < 8; nt++)
#pragma unroll
            for (int q = 0; q < 2; q++) {
                int cc = nt * 8 + (lane & 3) * 2 + q;
                a1v[nt * 2 + q] = av1[h * 128 + cc];
                a2v[nt * 2 + q] = av1[h * 128 + 64 + cc];
            }
#pragma unroll
        for (int mt = 0; mt < 2; mt++) {
            float s1a = 0.f, s2a = 0.f, s1b = 0.f, s2b = 0.f;
#pragma unroll
            for (int nt = 0; nt < 8; nt++)
#pragma unroll
                for (int q = 0; q < 2; q++) {
                    float a1 = a1v[nt * 2 + q], a2 = a2v[nt * 2 + q];
                    s1a += acc[mt][nt][q]     * a1;
                    s2a += acc[mt][nt][q]     * a2;
                    s1b += acc[mt][nt][2 + q] * a1;
                    s2b += acc[mt][nt][2 + q] * a2;
                }
#pragma unroll
            for (int off = 1; off <= 2; off <<= 1) {
                s1a += __shfl_xor_sync(0xffffffffu, s1a, off);
                s2a += __shfl_xor_sync(0xffffffffu, s2a, off);
                s1b += __shfl_xor_sync(0xffffffffu, s1b, off);
                s2b += __shfl_xor_sync(0xffffffffu, s2b, off);
            }
            if ((lane & 3) == 0) {
                int r0 = m0 + wm + mt * 16 + (lane >> 2);
                if (r0 < M) {
                    g_s1[r0 * 8 + h] = s1a;
                    g_s2[r0 * 8 + h] = s2a;
                }
                if (r0 + 8 < M) {
                    g_s1[(r0 + 8) * 8 + h] = s1b;
                    g_s2[(r0 + 8) * 8 + h] = s2b;
                }
            }
        }
    } else if (MODE == 2) {
        const float* a = (nb == 0) ? av1 : av2;
        float* t1 = (nb == 0) ? g_smu1 : g_slv1;
        float* t2 = (nb == 0) ? g_smu2 : g_slv2;
        float a1v[16], a2v[16];
#pragma unroll
        for (int nt = 0; nt < 8; nt++)
#pragma unroll
            for (int q = 0; q < 2; q++) {
                int cc = wn + nt * 8 + (lane & 3) * 2 + q;
                a1v[nt * 2 + q] = a[cc];
                a2v[nt * 2 + q] = a[128 + cc];
            }
#pragma unroll
        for (int mt = 0; mt < 2; mt++) {
            float s1a = 0.f, s2a = 0.f, s1b = 0.f, s2b = 0.f;
#pragma unroll
            for (int nt = 0; nt < 8; nt++)
#pragma unroll
                for (int q = 0; q < 2; q++) {
                    float a1 = a1v[nt * 2 + q], a2 = a2v[nt * 2 + q];
                    s1a += acc[mt][nt][q]     * a1;
                    s2a += acc[mt][nt][q]     * a2;
                    s1b += acc[mt][nt][2 + q] * a1;
                    s2b += acc[mt][nt][2 + q] * a2;
                }
#pragma unroll
            for (int off = 1; off <= 2; off <<= 1) {
                s1a += __shfl_xor_sync(0xffffffffu, s1a, off);
                s2a += __shfl_xor_sync(0xffffffffu, s2a, off);
                s1b += __shfl_xor_sync(0xffffffffu, s1b, off);
                s2b += __shfl_xor_sync(0xffffffffu, s2b, off);
            }
            if ((lane & 3) == 0) {
                int r0 = m0 + wm + mt * 16 + (lane >> 2);
                if (r0 < M) {
                    atomicAdd(&t1[r0], s1a);
                    atomicAdd(&t2[r0], s2a);
                }
                if (r0 + 8 < M) {
                    atomicAdd(&t1[r0 + 8], s1b);
                    atomicAdd(&t2[r0 + 8], s2b);
                }
            }
        }
    }
}

// ---------------- layer-1 aggregation: 2 warps/node, fp16 gather -----------
__global__ __launch_bounds__(256) void agg1_kernel(int N) {
    int gw = (blockIdx.x * 256 + threadIdx.x) >> 5;
    int n = gw >> 1;
    if (n >= N) return;
    const int lane = threadIdx.x & 31;
    const int sub = gw & 1;                    // column half: sub*256..+255
    const int le = lane >> 3, hh = lane & 7;   // weight phase: edge-in-4, head
    const int hme = sub * 4 + (lane >> 3);     // head of my 8 columns
    const int beg = g_rowptr[n];
    const int deg = g_rowptr[n + 1] - beg;

    const float s1v = g_s1[n * 8 + hh];
    float acc[8];
#pragma unroll
    for (int i = 0; i < 8; i++) acc[i] = 0.f;
    float den = 0.f;

    for (int eb = 0; eb < deg; eb += 4) {
        const int cnt = min(4, deg - eb);
        int d_le = g_col[beg + ((le < cnt) ? (eb + le) : 0)];
        float logit = s1v + g_s2[d_le * 8 + hh];
        float lr = logit > 0.f ? logit : 0.2f * logit;
        float w_le = __expf(-lr);
#pragma unroll 4
        for (int e = 0; e < cnt; e++) {
            int   d = __shfl_sync(0xffffffffu, d_le, e << 3);
            float w = __shfl_sync(0xffffffffu, w_le, (e << 3) + hme);
            uint4 pa = *(const uint4*)(g_hh + (size_t)d * X2DIM + sub * 256 + lane * 8);
            const __half2* ha = (const __half2*)&pa;
#pragma unroll
            for (int j = 0; j < 4; j++) {
                float2 fa = __half22float2(ha[j]);
                acc[2*j]     += w * fa.x;
                acc[2*j + 1] += w * fa.y;
            }
            den += w;
        }
    }

    const float inv = 1.f / den;
    __half hi[8];
#pragma unroll
    for (int i = 0; i < 8; i++) {
        float t = acc[i] * inv;
        t = t > 0.f ? t : expm1f(t);
        hi[i] = __float2half_rn(t);
    }
    *(uint4*)(g_x2h + (size_t)n * X2DIM + sub * 256 + lane * 8) = *(uint4*)(hi);
}

// ---------------- layer-2 aggregation: warp-per-node, fp16 gather ----------
__global__ __launch_bounds__(256) void agg2_kernel(
    const float* __restrict__ eps, float* __restrict__ out, int N)
{
    int n = (blockIdx.x * 256 + threadIdx.x) >> 5;
    if (n >= N) return;
    const int lane = threadIdx.x & 31;
    const int beg = g_rowptr[n];
    const int deg = g_rowptr[n + 1] - beg;
    const float bmu = g_smu1[n], blv = g_slv1[n];

    float amu[4] = {0,0,0,0}, alv[4] = {0,0,0,0};
    float dmu = 0.f, dlv = 0.f;

    for (int eb = 0; eb < deg; eb += 32) {
        const int cnt = min(32, deg - eb);
        int d_l = g_col[beg + ((lane < cnt) ? (eb + lane) : 0)];
        float lmu = bmu + g_smu2[d_l];
        float llv = blv + g_slv2[d_l];
        lmu = lmu > 0.f ? lmu : 0.2f * lmu;
        llv = llv > 0.f ? llv : 0.2f * llv;
        float wmu_l = __expf(-lmu);
        float wlv_l = __expf(-llv);
#pragma unroll 4
        for (int e = 0; e < cnt; e++) {
            int   d   = __shfl_sync(0xffffffffu, d_l,   e);
            float wmu = __shfl_sync(0xffffffffu, wmu_l, e);
            float wlv = __shfl_sync(0xffffffffu, wlv_l, e);
            const __half* base = g_hml + (size_t)d * 256;
            uint2 pm = *(const uint2*)(base + lane * 4);
            uint2 pl = *(const uint2*)(base + 128 + lane * 4);
            const __half2* hm = (const __half2*)&pm;
            const __half2* hl = (const __half2*)&pl;
            float2 m0 = __half22float2(hm[0]), m1 = __half22float2(hm[1]);
            float2 l0 = __half22float2(hl[0]), l1 = __half22float2(hl[1]);
            amu[0] += wmu * m0.x; amu[1] += wmu * m0.y;
            amu[2] += wmu * m1.x; amu[3] += wmu * m1.y;
            alv[0] += wlv * l0.x; alv[1] += wlv * l0.y;
            alv[2] += wlv * l1.x; alv[3] += wlv * l1.y;
            dmu += wmu; dlv += wlv;
        }
    }

    const float imu = 1.f / dmu, ilv = 1.f / dlv;
    float4 mu = make_float4(amu[0]*imu, amu[1]*imu, amu[2]*imu, amu[3]*imu);
    float4 lv = make_float4(alv[0]*ilv, alv[1]*ilv, alv[2]*ilv, alv[3]*ilv);
    float4 ev = *(const float4*)(eps + (size_t)n * NOUT + lane * 4);
    float4 z  = make_float4(ev.x * expf(lv.x) + mu.x,
                            ev.y * expf(lv.y) + mu.y,
                            ev.z * expf(lv.z) + mu.z,
                            ev.w * expf(lv.w) + mu.w);
    size_t NO = (size_t)N * NOUT;
    size_t o  = (size_t)n * NOUT + lane * 4;
    *(float4*)(out + o)          = z;
    *(float4*)(out + NO + o)     = mu;
    *(float4*)(out + 2 * NO + o) = lv;
}

// ---------------- host orchestration ----------------
extern "C" void kernel_launch(void* const* d_in, const int* in_sizes, int n_in,
                              void* d_out, int out_size)
{
    const float* x   = (const float*)d_in[0];
    const float* Ws  = (const float*)d_in[1];
    const float* As  = (const float*)d_in[2];
    const float* muW = (const float*)d_in[3];
    const float* mua = (const float*)d_in[4];
    const float* lvW = (const float*)d_in[5];
    const float* lva = (const float*)d_in[6];
    const float* eps = (const float*)d_in[7];
    const int*   ei  = (const int*)d_in[8];
    int E = in_sizes[8] / 2;
    int N = in_sizes[0] / NFEAT;
    float* out = (float*)d_out;

    __half *p_hh, *p_hml, *p_xh, *p_x2h, *p_bt1, *p_bt2;
    cudaGetSymbolAddress((void**)&p_hh,   g_hh);
    cudaGetSymbolAddress((void**)&p_hml,  g_hml);
    cudaGetSymbolAddress((void**)&p_xh,   g_xh);
    cudaGetSymbolAddress((void**)&p_x2h,  g_x2h);
    cudaGetSymbolAddress((void**)&p_bt1,  g_bt1);
    cudaGetSymbolAddress((void**)&p_bt2,  g_bt2);

    cudaFuncSetAttribute(gemm_tc<1>, cudaFuncAttributeMaxDynamicSharedMemorySize,
                         NSTAGE * STAGE);
    cudaFuncSetAttribute(gemm_tc<2>, cudaFuncAttributeMaxDynamicSharedMemorySize,
                         NSTAGE * STAGE);

    // side stream + events for graph-fork (created once; host-side resources)
    static cudaStream_t sB = nullptr;
    static cudaEvent_t eFork = nullptr, eJoin = nullptr;
    if (!sB) {
        cudaStreamCreateWithFlags(&sB, cudaStreamNonBlocking);
        cudaEventCreateWithFlags(&eFork, cudaEventDisableTiming);
        cudaEventCreateWithFlags(&eJoin, cudaEventDisableTiming);
    }

    int mtiles = (N + 127) / 128;
    int w1blocks = (2 * N + 7) / 8;    // agg1: 2 warps/node, 8 warps/block
    int w2blocks = (N + 7) / 8;        // agg2: 1 warp/node

    // fork: CSR chain + weight convert + scalar-target zeroing on side stream
    cudaEventRecord(eFork, 0);
    cudaStreamWaitEvent(sB, eFork, 0);

    convert_x_kernel<<<(N * NFEAT / 4 + 255) / 256, 256>>>(x, N * NFEAT / 4);       // 0
    convert_w_kernel<<<(512 * 512 + 256 * 512 + 255) / 256, 256, 0, sB>>>(Ws, muW, lvW); // 1 (sB)
    zero_kernel<<<(N + 255) / 256, 256, 0, sB>>>(N);                                 // 2 (sB)
    // gemm1 needs g_bt1 (converted on sB): join the weight-convert before it.
    hist_kernel<<<(E + 255) / 256, 256, 0, sB>>>(ei, E);                             // 3 (sB)
    cudaEventRecord(eJoin, sB);
    cudaStreamWaitEvent(0, eJoin, 0);  // main waits: bt1 ready (hist et al. ride along)
    gemm_tc<1><<<dim3(4, mtiles), 256, NSTAGE * STAGE>>>(p_xh, p_bt1, p_hh,          // 4
                                                         N, X2DIM, As, nullptr);
    scan_kernel<<<1, 1024, 0, sB>>>(N);                                              // 5 (sB)
    fill_kernel<<<(E + 255) / 256, 256, 0, sB>>>(ei, E);                             // 6 (sB)
    cudaEventRecord(eJoin, sB);

    cudaStreamWaitEvent(0, eJoin, 0);   // join: agg1 needs CSR (+zeroed targets)
    agg1_kernel<<<w1blocks, 256>>>(N);                                               // 7
    gemm_tc<2><<<dim3(2, mtiles), 256, NSTAGE * STAGE>>>(p_x2h, p_bt2, p_hml,        // 8
                                                         N, 256, mua, lva);
    agg2_kernel<<<w2blocks, 256>>>(eps, out, N);                                     // 9
}